// round 2
// baseline (speedup 1.0000x reference)
#include <cuda_runtime.h>
#include <math.h>

#define NN   100000
#define EE   400000
#define GG   2048
#define DIN  128
#define RANK 256

// ---------------- scratch (device globals: no allocations allowed) ----------
__device__ float g_hw  [NN * RANK];   // h @ W
__device__ float g_hact[NN * RANK];   // tanh(agg + b)   (pre-batchnorm)
__device__ int   g_cnt   [NN];
__device__ int   g_cursor[NN];
__device__ int   g_rowptr[NN + 1];
__device__ float g_dinv  [NN];
__device__ int   g_esrc[EE];
__device__ float g_ew  [EE];
__device__ int   g_gptr[GG + 1];
__device__ float g_sum  [RANK];
__device__ float g_sumsq[RANK];
__device__ float g_scale[RANK];
__device__ float g_shift[RANK];
__device__ int   g_part[128];

// ---------------- graph preprocessing (once per call) -----------------------
__global__ void k_init() {
    int i = blockIdx.x * blockDim.x + threadIdx.x;
    if (i < NN) { g_cnt[i] = 0; g_cursor[i] = 0; }
    if (i < RANK) { g_sum[i] = 0.f; g_sumsq[i] = 0.f; }
}

__global__ void k_hist(const int* __restrict__ dst) {
    int e = blockIdx.x * blockDim.x + threadIdx.x;
    if (e < EE) atomicAdd(&g_cnt[dst[e]], 1);
}

__global__ void k_dinv() {
    int v = blockIdx.x * blockDim.x + threadIdx.x;
    if (v == 0) g_rowptr[NN] = EE;
    if (v < NN) g_dinv[v] = rsqrtf((float)(g_cnt[v] + 1));  // +1 self loop
}

// exclusive scan of g_cnt -> g_rowptr  (1024 elems / block, 98 blocks)
__global__ void k_scan1() {
    __shared__ int sm[256];
    int b = blockIdx.x, t = threadIdx.x;
    int base = b * 1024 + t * 4;
    int s = 0;
    #pragma unroll
    for (int j = 0; j < 4; j++) { int i = base + j; if (i < NN) s += g_cnt[i]; }
    sm[t] = s; __syncthreads();
    for (int off = 128; off > 0; off >>= 1) {
        if (t < off) sm[t] += sm[t + off];
        __syncthreads();
    }
    if (t == 0) g_part[b] = sm[0];
}

__global__ void k_scan2() {
    __shared__ int sm[128];
    int t = threadIdx.x;
    int v = (t < 98) ? g_part[t] : 0;
    sm[t] = v; __syncthreads();
    for (int off = 1; off < 128; off <<= 1) {
        int u = (t >= off) ? sm[t - off] : 0;
        __syncthreads();
        sm[t] += u;
        __syncthreads();
    }
    if (t < 98) g_part[t] = sm[t] - v;   // exclusive
}

__global__ void k_scan3() {
    __shared__ int sm[256];
    int b = blockIdx.x, t = threadIdx.x;
    int base = b * 1024 + t * 4;
    int v[4]; int s = 0;
    #pragma unroll
    for (int j = 0; j < 4; j++) { int i = base + j; v[j] = (i < NN) ? g_cnt[i] : 0; s += v[j]; }
    sm[t] = s; __syncthreads();
    for (int off = 1; off < 256; off <<= 1) {
        int u = (t >= off) ? sm[t - off] : 0;
        __syncthreads();
        sm[t] += u;
        __syncthreads();
    }
    int off0 = g_part[b] + (sm[t] - s);  // block offset + thread-exclusive
    int run = 0;
    #pragma unroll
    for (int j = 0; j < 4; j++) {
        int i = base + j;
        if (i < NN) g_rowptr[i] = off0 + run;
        run += v[j];
    }
}

__global__ void k_gptr(const int* __restrict__ batch) {
    int i = blockIdx.x * blockDim.x + threadIdx.x;
    if (i >= NN) return;
    int bi = batch[i];
    if (i == 0) {
        for (int g = 0; g <= bi; g++) g_gptr[g] = 0;
    } else {
        int bp = batch[i - 1];
        for (int g = bp + 1; g <= bi; g++) g_gptr[g] = i;
    }
    if (i == NN - 1) {
        for (int g = bi + 1; g <= GG; g++) g_gptr[g] = NN;
    }
}

__global__ void k_scatter(const int* __restrict__ src, const int* __restrict__ dst) {
    int e = blockIdx.x * blockDim.x + threadIdx.x;
    if (e >= EE) return;
    int s = src[e], d = dst[e];
    int pos = g_rowptr[d] + atomicAdd(&g_cursor[d], 1);
    g_esrc[pos] = s;
    g_ew[pos]   = g_dinv[s] * g_dinv[d];
}

// ---------------- SGEMM: g_hw = A @ W, A = X (layer0) or bn(g_hact) ---------
// BM=BN=128, BK=8, 256 threads, 8x8 per thread.
__global__ void __launch_bounds__(256, 2)
k_gemm(const float* __restrict__ X, const float* __restrict__ W,
       int K, int useNorm) {
    __shared__ float As[8][128];
    __shared__ float Bs[8][128];
    int tid = threadIdx.x;
    int brow = blockIdx.x * 128, bcol = blockIdx.y * 128;
    int tx = tid & 15, ty = tid >> 4;
    int arow = tid >> 1, ak = (tid & 1) * 4;
    int brw = tid >> 5, bc = (tid & 31) * 4;

    float acc[8][8];
    #pragma unroll
    for (int i = 0; i < 8; i++)
        #pragma unroll
        for (int j = 0; j < 8; j++) acc[i][j] = 0.f;

    const float* Aptr = useNorm ? g_hact : X;

    for (int k0 = 0; k0 < K; k0 += 8) {
        int r = brow + arow;
        float4 a = make_float4(0.f, 0.f, 0.f, 0.f);
        if (r < NN) a = *(const float4*)(Aptr + r * K + k0 + ak);
        if (useNorm) {
            int kb = k0 + ak;
            a.x = fmaf(a.x, g_scale[kb + 0], g_shift[kb + 0]);
            a.y = fmaf(a.y, g_scale[kb + 1], g_shift[kb + 1]);
            a.z = fmaf(a.z, g_scale[kb + 2], g_shift[kb + 2]);
            a.w = fmaf(a.w, g_scale[kb + 3], g_shift[kb + 3]);
        }
        As[ak + 0][arow] = a.x;
        As[ak + 1][arow] = a.y;
        As[ak + 2][arow] = a.z;
        As[ak + 3][arow] = a.w;

        *(float4*)&Bs[brw][bc] = *(const float4*)(W + (k0 + brw) * RANK + bcol + bc);
        __syncthreads();

        #pragma unroll
        for (int kk = 0; kk < 8; kk++) {
            float ra[8], rb[8];
            *(float4*)&ra[0] = *(const float4*)&As[kk][ty * 8];
            *(float4*)&ra[4] = *(const float4*)&As[kk][ty * 8 + 4];
            *(float4*)&rb[0] = *(const float4*)&Bs[kk][tx * 8];
            *(float4*)&rb[4] = *(const float4*)&Bs[kk][tx * 8 + 4];
            #pragma unroll
            for (int i = 0; i < 8; i++)
                #pragma unroll
                for (int j = 0; j < 8; j++)
                    acc[i][j] = fmaf(ra[i], rb[j], acc[i][j]);
        }
        __syncthreads();
    }

    #pragma unroll
    for (int i = 0; i < 8; i++) {
        int r = brow + ty * 8 + i;
        if (r < NN) {
            *(float4*)(g_hw + r * RANK + bcol + tx * 8) =
                make_float4(acc[i][0], acc[i][1], acc[i][2], acc[i][3]);
            *(float4*)(g_hw + r * RANK + bcol + tx * 8 + 4) =
                make_float4(acc[i][4], acc[i][5], acc[i][6], acc[i][7]);
        }
    }
}

// ---------------- aggregation + bias + tanh + BN stats ----------------------
#define NPB 32
__global__ void __launch_bounds__(RANK)
k_agg(const float* __restrict__ bias) {
    int c = threadIdx.x;            // column 0..255
    int v0 = blockIdx.x * NPB;
    float bc = bias[c];
    float s = 0.f, s2 = 0.f;
    for (int n = 0; n < NPB; n++) {
        int v = v0 + n;
        if (v >= NN) break;
        int beg = g_rowptr[v], end = g_rowptr[v + 1];
        float di = g_dinv[v];
        float acc = di * di * g_hw[v * RANK + c];   // self loop
        for (int e = beg; e < end; e++) {
            acc = fmaf(g_ew[e], g_hw[g_esrc[e] * RANK + c], acc);
        }
        float h = tanhf(acc + bc);
        g_hact[v * RANK + c] = h;
        s += h; s2 = fmaf(h, h, s2);
    }
    atomicAdd(&g_sum[c], s);
    atomicAdd(&g_sumsq[c], s2);
}

__global__ void k_bnfinal(const float* __restrict__ gamma,
                          const float* __restrict__ beta) {
    int c = threadIdx.x;
    float mu  = g_sum[c]   * (1.0f / NN);
    float var = g_sumsq[c] * (1.0f / NN) - mu * mu;
    float sc  = gamma[c] * rsqrtf(var + 1e-5f);
    g_scale[c] = sc;
    g_shift[c] = beta[c] - mu * sc;
    g_sum[c] = 0.f; g_sumsq[c] = 0.f;      // ready for next layer
}

__global__ void k_pool(float* __restrict__ out) {
    int g = blockIdx.x, c = threadIdx.x;
    int beg = g_gptr[g], end = g_gptr[g + 1];
    float sc = g_scale[c], sh = g_shift[c];
    float m = -INFINITY;
    for (int r = beg; r < end; r++)
        m = fmaxf(m, fmaf(sc, g_hact[r * RANK + c], sh));
    out[g * RANK + c] = (end > beg) ? m : 0.0f;
}

// ---------------- launch ----------------------------------------------------
extern "C" void kernel_launch(void* const* d_in, const int* in_sizes, int n_in,
                              void* d_out, int out_size) {
    const float* x     = (const float*)d_in[0];
    const int*   ei    = (const int*)  d_in[1];   // [2, E] int32 (JAX default x64-off)
    const int*   batch = (const int*)  d_in[2];
    const float* W[3]     = { (const float*)d_in[3],  (const float*)d_in[7],  (const float*)d_in[11] };
    const float* b[3]     = { (const float*)d_in[4],  (const float*)d_in[8],  (const float*)d_in[12] };
    const float* gamma[3] = { (const float*)d_in[5],  (const float*)d_in[9],  (const float*)d_in[13] };
    const float* beta[3]  = { (const float*)d_in[6],  (const float*)d_in[10], (const float*)d_in[14] };
    const int* src = ei;
    const int* dst = ei + EE;
    float* out = (float*)d_out;

    k_init   <<<(NN + 255) / 256, 256>>>();
    k_hist   <<<(EE + 255) / 256, 256>>>(dst);
    k_dinv   <<<(NN + 255) / 256, 256>>>();
    k_scan1  <<<98, 256>>>();
    k_scan2  <<<1, 128>>>();
    k_scan3  <<<98, 256>>>();
    k_gptr   <<<(NN + 255) / 256, 256>>>(batch);
    k_scatter<<<(EE + 255) / 256, 256>>>(src, dst);

    dim3 gemm_grid((NN + 127) / 128, RANK / 128);
    for (int l = 0; l < 3; l++) {
        int K = (l == 0) ? DIN : RANK;
        k_gemm<<<gemm_grid, 256>>>(x, W[l], K, l > 0);
        k_agg <<<(NN + NPB - 1) / NPB, RANK>>>(b[l]);
        k_bnfinal<<<1, RANK>>>(gamma[l], beta[l]);
        k_pool<<<GG, RANK>>>(out + (size_t)l * GG * RANK);
    }
}